// round 11
// baseline (speedup 1.0000x reference)
#include <cuda_runtime.h>

// ---------------------------------------------------------------------------
// GraphSAGE 3-layer, fp32. N=50000, E=600000, 128->128->128->40.
//   CSR build per call (proven R7)
//   Layers 1,2: FFMA2 GEMM with split-W smem layout (2x conflict-free LDS.128)
//   Layer 3:    FFMA2 GEMM (proven R2 form)
//   Aggregation: fused CSR gather+combine, 4-way MLP (proven R7)
// NOTE: tcgen05 is NOT available in this harness build (compute_103 PTX target).
// ---------------------------------------------------------------------------

#define MAXN 50000
#define MAXE 600000

static __device__ float g_TS [MAXN * 256];
static __device__ float g_H  [MAXN * 128];
static __device__ float g_rdeg[MAXN];
static __device__ int   g_degi[MAXN];
static __device__ int   g_off [MAXN + 1];
static __device__ int   g_cur [MAXN];
static __device__ int   g_esrc[MAXE];
static __device__ int   g_bsum[256];

__device__ __forceinline__ unsigned long long pack2(float x) {
    unsigned long long r;
    asm("mov.b64 %0, {%1, %1};" : "=l"(r) : "f"(x));
    return r;
}
__device__ __forceinline__ void ffma2(unsigned long long& d,
                                      unsigned long long a,
                                      unsigned long long b) {
    asm("fma.rn.f32x2 %0, %1, %2, %0;" : "+l"(d) : "l"(a), "l"(b));
}
union U2F2 { unsigned long long u; float2 f; };

// ---------------------------------------------------------------------------
// CSR build (proven R7)
// ---------------------------------------------------------------------------
__global__ void zero_i(int* p, int n) {
    int i = blockIdx.x * blockDim.x + threadIdx.x;
    if (i < n) p[i] = 0;
}
__global__ void count_deg(const int* __restrict__ dst, int E) {
    int i = blockIdx.x * blockDim.x + threadIdx.x;
    if (i < E) atomicAdd(&g_degi[dst[i]], 1);
}
__global__ void scan_block(const int* __restrict__ in, int* __restrict__ out,
                           int* bsum, int n) {
    int i = blockIdx.x * 256 + threadIdx.x;
    int lane = threadIdx.x & 31, w = threadIdx.x >> 5;
    int v = (i < n) ? in[i] : 0;
    int incl = v;
#pragma unroll
    for (int d = 1; d < 32; d <<= 1) {
        int t = __shfl_up_sync(0xffffffffu, incl, d);
        if (lane >= d) incl += t;
    }
    __shared__ int ws[8];
    if (lane == 31) ws[w] = incl;
    __syncthreads();
    if (threadIdx.x < 8) {
        int x = ws[threadIdx.x];
        int in2 = x;
#pragma unroll
        for (int d = 1; d < 8; d <<= 1) {
            int t = __shfl_up_sync(0xffu, in2, d);
            if (threadIdx.x >= (unsigned)d) in2 += t;
        }
        ws[threadIdx.x] = in2 - x;
        if (threadIdx.x == 7 && bsum) bsum[blockIdx.x] = in2;
    }
    __syncthreads();
    if (i < n) out[i] = ws[w] + incl - v;
}
__global__ void add_off(int M, int E) {
    int i = blockIdx.x * blockDim.x + threadIdx.x;
    if (i < M) {
        int o = g_off[i] + g_bsum[i >> 8];
        g_off[i] = o;
        g_cur[i] = o;
    } else if (i == M) {
        g_off[M] = E;
    }
}
__global__ void scatter_edges(const int* __restrict__ src,
                              const int* __restrict__ dst, int E) {
    int e = blockIdx.x * blockDim.x + threadIdx.x;
    if (e < E) {
        int slot = atomicAdd(&g_cur[dst[e]], 1);
        g_esrc[slot] = src[e];
    }
}
__global__ void make_rdeg(int M) {
    int i = blockIdx.x * blockDim.x + threadIdx.x;
    if (i < M) g_rdeg[i] = 1.0f / fmaxf((float)g_degi[i], 1.0f);
}

// ---------------------------------------------------------------------------
// GEMM 128->256: out[M x 256] = A[M x 128] @ [Wn | Ws]
// Identical to R2 except the W smem layout/loads:
//   row k (256 words): word = pair*128 + ct*4 + j holds column ct*8 + pair*4 + j
//   -> two LDS.128 per k, per-lane stride 4 words -> CONFLICT-FREE.
// Inner-loop shape (w[4] ulls, 8 broadcast A loads, 32 ffma2) unchanged.
// ---------------------------------------------------------------------------
__global__ void __launch_bounds__(512, 1)
gemm128(const float* __restrict__ A,
        const float* __restrict__ Wn,
        const float* __restrict__ Ws,
        float* __restrict__ out, int M) {
    constexpr int ASTR = 132;
    extern __shared__ float sm[];
    float* Wsh = sm;               // 128 x 256 (split-pair layout)
    float* Ash = sm + 128 * 256;   // 128 x ASTR

    const int tid = threadIdx.x;
    const int row0 = blockIdx.x * 128;

    // stage W: i enumerates (k, g) with g = 4-column group 0..63
    for (int i = tid; i < 128 * 64; i += 512) {
        int k = i >> 6;
        int g = i & 63;
        float4 wv;
        if (g < 32) wv = *reinterpret_cast<const float4*>(Wn + k * 128 + g * 4);
        else        wv = *reinterpret_cast<const float4*>(Ws + k * 128 + (g - 32) * 4);
        int word = ((g & 1) << 7) + (g >> 1) * 4;
        *reinterpret_cast<float4*>(Wsh + k * 256 + word) = wv;
    }
    // stage A tile (row-major, padded stride) — identical to R2
    for (int i = tid; i < 128 * 32; i += 512) {
        int r = i >> 5;
        int kc = (i & 31) * 4;
        int gr = row0 + r;
        if (gr >= M) gr = M - 1;
        float4 a = *reinterpret_cast<const float4*>(A + (size_t)gr * 128 + kc);
        *reinterpret_cast<float4*>(Ash + r * ASTR + kc) = a;
    }
    __syncthreads();

    const int ct = tid & 31;
    const int rt = tid >> 5;
    const int colbase = ct * 8;
    const float* arow = Ash + rt * 8 * ASTR;

    unsigned long long acc[8][4];
#pragma unroll
    for (int i = 0; i < 8; i++)
#pragma unroll
        for (int p = 0; p < 4; p++) acc[i][p] = 0ull;

#pragma unroll 4
    for (int k = 0; k < 128; ++k) {
        unsigned long long w[4];
        ulonglong2 va = *reinterpret_cast<const ulonglong2*>(Wsh + k * 256 + ct * 4);
        ulonglong2 vb = *reinterpret_cast<const ulonglong2*>(Wsh + k * 256 + 128 + ct * 4);
        w[0] = va.x; w[1] = va.y; w[2] = vb.x; w[3] = vb.y;
#pragma unroll
        for (int i = 0; i < 8; i++) {
            unsigned long long aa = pack2(arow[i * ASTR + k]);
#pragma unroll
            for (int p = 0; p < 4; p++) ffma2(acc[i][p], aa, w[p]);
        }
    }

    // epilogue: w[0]=cols colbase..+1, w[1]=+2..3 (va), w[2]=+4..5, w[3]=+6..7 (vb)
#pragma unroll
    for (int i = 0; i < 8; i++) {
        int gr = row0 + rt * 8 + i;
        if (gr < M) {
            float* o = out + (size_t)gr * 256 + colbase;
#pragma unroll
            for (int p = 0; p < 4; p += 2) {
                U2F2 u0, u1;
                u0.u = acc[i][p];
                u1.u = acc[i][p + 1];
                *reinterpret_cast<float4*>(o + 2 * p) =
                    make_float4(u0.f.x, u0.f.y, u1.f.x, u1.f.y);
            }
        }
    }
}

// ---------------------------------------------------------------------------
// FFMA2 GEMM for layer 3 (proven R2 form)
// ---------------------------------------------------------------------------
template <int DOUT, int CT, int RT, int TM, int TNP>
__global__ void __launch_bounds__(CT * RT, 1)
gemm_fused(const float* __restrict__ A,
           const float* __restrict__ Wn,
           const float* __restrict__ Ws,
           float* __restrict__ out, int M) {
    constexpr int NOUT = 2 * DOUT;
    constexpr int BM = RT * TM;
    constexpr int NT = CT * RT;
    constexpr int ASTR = 132;

    extern __shared__ float smf[];
    float* Wsh = smf;
    float* Ash = smf + 128 * NOUT;

    const int tid = threadIdx.x;
    const int row0 = blockIdx.x * BM;

    for (int i = tid; i < 128 * (DOUT / 4); i += NT) {
        int k = i / (DOUT / 4);
        int c = (i % (DOUT / 4)) * 4;
        float4 wn = *reinterpret_cast<const float4*>(Wn + k * DOUT + c);
        float4 ws = *reinterpret_cast<const float4*>(Ws + k * DOUT + c);
        *reinterpret_cast<float4*>(Wsh + k * NOUT + c) = wn;
        *reinterpret_cast<float4*>(Wsh + k * NOUT + DOUT + c) = ws;
    }
    for (int i = tid; i < BM * 32; i += NT) {
        int r = i / 32;
        int kc = (i % 32) * 4;
        int gr = row0 + r;
        if (gr >= M) gr = M - 1;
        float4 a = *reinterpret_cast<const float4*>(A + (size_t)gr * 128 + kc);
        *reinterpret_cast<float4*>(Ash + r * ASTR + kc) = a;
    }
    __syncthreads();

    const int ct = tid % CT;
    const int rt = tid / CT;
    const int colbase = ct * (TNP * 2);
    const float* arow = Ash + rt * TM * ASTR;

    unsigned long long acc[TM][TNP];
#pragma unroll
    for (int i = 0; i < TM; i++)
#pragma unroll
        for (int p = 0; p < TNP; p++) acc[i][p] = 0ull;

#pragma unroll 4
    for (int k = 0; k < 128; ++k) {
        unsigned long long w[TNP];
#pragma unroll
        for (int p = 0; p < TNP; p++)
            w[p] = *reinterpret_cast<const unsigned long long*>(
                Wsh + k * NOUT + colbase + 2 * p);
#pragma unroll
        for (int i = 0; i < TM; i++) {
            unsigned long long aa = pack2(arow[i * ASTR + k]);
#pragma unroll
            for (int p = 0; p < TNP; p++) ffma2(acc[i][p], aa, w[p]);
        }
    }

#pragma unroll
    for (int i = 0; i < TM; i++) {
        int gr = row0 + rt * TM + i;
        if (gr < M) {
            float* o = out + (size_t)gr * NOUT + colbase;
#pragma unroll
            for (int p = 0; p < TNP; p += 2) {
                U2F2 u0, u1;
                u0.u = acc[i][p];
                u1.u = acc[i][p + 1];
                *reinterpret_cast<float4*>(o + 2 * p) =
                    make_float4(u0.f.x, u0.f.y, u1.f.x, u1.f.y);
            }
        }
    }
}

// ---------------------------------------------------------------------------
// Fused CSR aggregate + combine (proven R7)
// ---------------------------------------------------------------------------
template <bool RELU>
__global__ void aggcomb128(const float* __restrict__ TS,
                           const float* __restrict__ b,
                           float* __restrict__ out, int M) {
    int n = blockIdx.x * 8 + (threadIdx.x >> 5);
    if (n >= M) return;
    int lane = threadIdx.x & 31;
    int beg = g_off[n], end = g_off[n + 1];

    float4 a0 = make_float4(0.f, 0.f, 0.f, 0.f);
    float4 a1 = make_float4(0.f, 0.f, 0.f, 0.f);
    float4 a2 = make_float4(0.f, 0.f, 0.f, 0.f);
    float4 a3 = make_float4(0.f, 0.f, 0.f, 0.f);

    for (int j0 = beg; j0 < end; j0 += 32) {
        int cnt = min(32, end - j0);
        int s = (lane < cnt) ? g_esrc[j0 + lane] : 0;
        int t = 0;
        for (; t + 3 < cnt; t += 4) {
            int s0 = __shfl_sync(0xffffffffu, s, t);
            int s1 = __shfl_sync(0xffffffffu, s, t + 1);
            int s2 = __shfl_sync(0xffffffffu, s, t + 2);
            int s3 = __shfl_sync(0xffffffffu, s, t + 3);
            float4 v0 = *reinterpret_cast<const float4*>(TS + (size_t)s0 * 256 + lane * 4);
            float4 v1 = *reinterpret_cast<const float4*>(TS + (size_t)s1 * 256 + lane * 4);
            float4 v2 = *reinterpret_cast<const float4*>(TS + (size_t)s2 * 256 + lane * 4);
            float4 v3 = *reinterpret_cast<const float4*>(TS + (size_t)s3 * 256 + lane * 4);
            a0.x += v0.x; a0.y += v0.y; a0.z += v0.z; a0.w += v0.w;
            a1.x += v1.x; a1.y += v1.y; a1.z += v1.z; a1.w += v1.w;
            a2.x += v2.x; a2.y += v2.y; a2.z += v2.z; a2.w += v2.w;
            a3.x += v3.x; a3.y += v3.y; a3.z += v3.z; a3.w += v3.w;
        }
        for (; t < cnt; ++t) {
            int s0 = __shfl_sync(0xffffffffu, s, t);
            float4 v0 = *reinterpret_cast<const float4*>(TS + (size_t)s0 * 256 + lane * 4);
            a0.x += v0.x; a0.y += v0.y; a0.z += v0.z; a0.w += v0.w;
        }
    }
    float r = g_rdeg[n];
    float4 sf = *reinterpret_cast<const float4*>(TS + (size_t)n * 256 + 128 + lane * 4);
    float4 bb = *reinterpret_cast<const float4*>(b + lane * 4);
    float4 v;
    v.x = sf.x + (a0.x + a1.x + a2.x + a3.x) * r + bb.x;
    v.y = sf.y + (a0.y + a1.y + a2.y + a3.y) * r + bb.y;
    v.z = sf.z + (a0.z + a1.z + a2.z + a3.z) * r + bb.z;
    v.w = sf.w + (a0.w + a1.w + a2.w + a3.w) * r + bb.w;
    if (RELU) {
        v.x = fmaxf(v.x, 0.f); v.y = fmaxf(v.y, 0.f);
        v.z = fmaxf(v.z, 0.f); v.w = fmaxf(v.w, 0.f);
    }
    *reinterpret_cast<float4*>(out + (size_t)n * 128 + lane * 4) = v;
}

__global__ void aggcomb40(const float* __restrict__ TS,
                          const float* __restrict__ b,
                          float* __restrict__ out, int M) {
    int n = blockIdx.x * 8 + (threadIdx.x >> 5);
    if (n >= M) return;
    int lane = threadIdx.x & 31;
    int beg = g_off[n], end = g_off[n + 1];
    bool act = lane < 10;
    int laneo = act ? lane : 0;

    float4 a0 = make_float4(0.f, 0.f, 0.f, 0.f);
    float4 a1 = make_float4(0.f, 0.f, 0.f, 0.f);
    float4 a2 = make_float4(0.f, 0.f, 0.f, 0.f);
    float4 a3 = make_float4(0.f, 0.f, 0.f, 0.f);

    for (int j0 = beg; j0 < end; j0 += 32) {
        int cnt = min(32, end - j0);
        int s = (lane < cnt) ? g_esrc[j0 + lane] : 0;
        int t = 0;
        for (; t + 3 < cnt; t += 4) {
            int s0 = __shfl_sync(0xffffffffu, s, t);
            int s1 = __shfl_sync(0xffffffffu, s, t + 1);
            int s2 = __shfl_sync(0xffffffffu, s, t + 2);
            int s3 = __shfl_sync(0xffffffffu, s, t + 3);
            float4 v0 = *reinterpret_cast<const float4*>(TS + (size_t)s0 * 80 + laneo * 4);
            float4 v1 = *reinterpret_cast<const float4*>(TS + (size_t)s1 * 80 + laneo * 4);
            float4 v2 = *reinterpret_cast<const float4*>(TS + (size_t)s2 * 80 + laneo * 4);
            float4 v3 = *reinterpret_cast<const float4*>(TS + (size_t)s3 * 80 + laneo * 4);
            a0.x += v0.x; a0.y += v0.y; a0.z += v0.z; a0.w += v0.w;
            a1.x += v1.x; a1.y += v1.y; a1.z += v1.z; a1.w += v1.w;
            a2.x += v2.x; a2.y += v2.y; a2.z += v2.z; a2.w += v2.w;
            a3.x += v3.x; a3.y += v3.y; a3.z += v3.z; a3.w += v3.w;
        }
        for (; t < cnt; ++t) {
            int s0 = __shfl_sync(0xffffffffu, s, t);
            float4 v0 = *reinterpret_cast<const float4*>(TS + (size_t)s0 * 80 + laneo * 4);
            a0.x += v0.x; a0.y += v0.y; a0.z += v0.z; a0.w += v0.w;
        }
    }
    if (act) {
        float r = g_rdeg[n];
        float4 sf = *reinterpret_cast<const float4*>(TS + (size_t)n * 80 + 40 + lane * 4);
        float4 bb = *reinterpret_cast<const float4*>(b + lane * 4);
        float4 v;
        v.x = sf.x + (a0.x + a1.x + a2.x + a3.x) * r + bb.x;
        v.y = sf.y + (a0.y + a1.y + a2.y + a3.y) * r + bb.y;
        v.z = sf.z + (a0.z + a1.z + a2.z + a3.z) * r + bb.z;
        v.w = sf.w + (a0.w + a1.w + a2.w + a3.w) * r + bb.w;
        *reinterpret_cast<float4*>(out + (size_t)n * 40 + lane * 4) = v;
    }
}

// ---------------------------------------------------------------------------
// launch
// ---------------------------------------------------------------------------
static inline int cdiv(int a, int b) { return (a + b - 1) / b; }

extern "C" void kernel_launch(void* const* d_in, const int* in_sizes, int n_in,
                              void* d_out, int out_size) {
    const float* feat = (const float*)d_in[0];
    const int*   src  = (const int*)d_in[1];
    const int*   dst  = (const int*)d_in[2];
    const float* wS0 = (const float*)d_in[3];
    const float* wN0 = (const float*)d_in[4];
    const float* b0  = (const float*)d_in[5];
    const float* wS1 = (const float*)d_in[6];
    const float* wN1 = (const float*)d_in[7];
    const float* b1  = (const float*)d_in[8];
    const float* wS2 = (const float*)d_in[9];
    const float* wN2 = (const float*)d_in[10];
    const float* b2  = (const float*)d_in[11];
    float* out = (float*)d_out;

    const int M = in_sizes[0] / 128;
    const int E = in_sizes[1];

    void *pTS, *pH, *pDegi, *pOff, *pBsum;
    cudaGetSymbolAddress(&pTS, g_TS);
    cudaGetSymbolAddress(&pH, g_H);
    cudaGetSymbolAddress(&pDegi, g_degi);
    cudaGetSymbolAddress(&pOff, g_off);
    cudaGetSymbolAddress(&pBsum, g_bsum);
    float* TS = (float*)pTS;
    float* H = (float*)pH;
    int* degi = (int*)pDegi;
    int* off = (int*)pOff;
    int* bsum = (int*)pBsum;

    constexpr int SMEM_A = (128 * 256 + 128 * 132) * 4;  // 198656 B
    constexpr int SMEM_B = (128 * 80 + 128 * 132) * 4;   // 108544 B
    static bool attr_done = false;
    if (!attr_done) {
        cudaFuncSetAttribute((const void*)gemm128,
                             cudaFuncAttributeMaxDynamicSharedMemorySize, SMEM_A);
        cudaFuncSetAttribute((const void*)gemm_fused<40, 10, 32, 4, 4>,
                             cudaFuncAttributeMaxDynamicSharedMemorySize, SMEM_B);
        attr_done = true;
    }

    const int gemm_blocks = cdiv(M, 128);
    const int nscan = cdiv(M, 256);
    const int node_blocks = cdiv(M, 8);

    // ---- CSR build ----
    zero_i<<<cdiv(M, 256), 256>>>(degi, M);
    count_deg<<<cdiv(E, 256), 256>>>(dst, E);
    scan_block<<<nscan, 256>>>(degi, off, bsum, M);
    scan_block<<<1, 256>>>(bsum, bsum, nullptr, nscan);
    add_off<<<cdiv(M + 1, 256), 256>>>(M, E);
    scatter_edges<<<cdiv(E, 256), 256>>>(src, dst, E);
    make_rdeg<<<cdiv(M, 256), 256>>>(M);

    // ---- layer 1 ----
    gemm128<<<gemm_blocks, 512, SMEM_A>>>(feat, wN0, wS0, TS, M);
    aggcomb128<true><<<node_blocks, 256>>>(TS, b0, H, M);

    // ---- layer 2 ----
    gemm128<<<gemm_blocks, 512, SMEM_A>>>(H, wN1, wS1, TS, M);
    aggcomb128<true><<<node_blocks, 256>>>(TS, b1, H, M);

    // ---- layer 3 ----
    gemm_fused<40, 10, 32, 4, 4><<<gemm_blocks, 320, SMEM_B>>>(H, wN2, wS2, TS, M);
    aggcomb40<<<node_blocks, 256>>>(TS, b2, out, M);
}